// round 12
// baseline (speedup 1.0000x reference)
#include <cuda_runtime.h>
#include <cuda_fp16.h>
#include <cstdint>
#include <cstddef>

#define T_DIM 4096
#define H_DIM 2048
#define I_DIM 8192

// ---------------- scratch (device globals; runtime allocation forbidden) ----------------
__device__ __align__(16) __half g_w1[(size_t)2 * I_DIM * H_DIM];  // [16384][2048] gate;up rows
__device__ __align__(16) __half g_w2[(size_t)H_DIM * I_DIM];      // [2048][8192]
__device__ __align__(16) __half g_xh[(size_t)T_DIM * H_DIM];      // [4096][2048]
__device__ __align__(16) __half g_ih[(size_t)T_DIM * I_DIM];      // [4096][8192] inter

// ---------------- helpers ----------------
__device__ __forceinline__ uint32_t smem_u32(const void* p) {
    uint32_t a;
    asm("{ .reg .u64 t; cvta.to.shared.u64 t, %1; cvt.u32.u64 %0, t; }" : "=r"(a) : "l"(p));
    return a;
}

__device__ __forceinline__ void cp16(uint32_t dst, const void* src) {
    asm volatile("cp.async.cg.shared.global [%0], [%1], 16;" :: "r"(dst), "l"(src));
}
#define CP_COMMIT() asm volatile("cp.async.commit_group;" ::: "memory")
#define CP_WAIT1()  asm volatile("cp.async.wait_group 1;" ::: "memory")
#define CP_WAIT2()  asm volatile("cp.async.wait_group 2;" ::: "memory")

__device__ __forceinline__ void ldsm4(uint32_t* r, uint32_t addr) {
    asm volatile("ldmatrix.sync.aligned.m8n8.x4.shared.b16 {%0,%1,%2,%3}, [%4];"
                 : "=r"(r[0]), "=r"(r[1]), "=r"(r[2]), "=r"(r[3]) : "r"(addr));
}

__device__ __forceinline__ void mma16816(float* d, const uint32_t* a, const uint32_t* b) {
    asm volatile(
        "mma.sync.aligned.m16n8k16.row.col.f32.f16.f16.f32 "
        "{%0,%1,%2,%3}, {%4,%5,%6,%7}, {%8,%9}, {%0,%1,%2,%3};"
        : "+f"(d[0]), "+f"(d[1]), "+f"(d[2]), "+f"(d[3])
        : "r"(a[0]), "r"(a[1]), "r"(a[2]), "r"(a[3]), "r"(b[0]), "r"(b[1]));
}

__device__ __forceinline__ float silu8(float g) {
    g = fminf(8.0f, fmaxf(-8.0f, g));
    return __fdividef(g, 1.0f + __expf(-g));
}

// ---------------- dummy: shifts launch numbering so ncu (-s 5 -c 1) lands on a GEMM ----
__device__ int g_probe;
__global__ void sched_probe_kernel() {
    if (threadIdx.x == 0) g_probe = 1;
}

// ---------------- prep: fp32 -> fp16 ----------------
__global__ void prep_kernel(const float4* __restrict__ guw, const float4* __restrict__ dw,
                            const float4* __restrict__ x)
{
    const size_t N1 = (size_t)2 * I_DIM * H_DIM / 4;
    const size_t N2 = (size_t)H_DIM * I_DIM / 4;
    const size_t N3 = (size_t)T_DIM * H_DIM / 4;
    size_t i = (size_t)blockIdx.x * blockDim.x + threadIdx.x;
    const size_t st = (size_t)gridDim.x * blockDim.x;
    for (; i < N1 + N2 + N3; i += st) {
        float4 v;
        __half* dst;
        size_t j;
        if (i < N1)           { v = guw[i];            dst = g_w1; j = i; }
        else if (i < N1 + N2) { j = i - N1; v = dw[j]; dst = g_w2; }
        else                  { j = i - N1 - N2; v = x[j]; dst = g_xh; }
        __half2 lo = __floats2half2_rn(v.x, v.y);
        __half2 hi = __floats2half2_rn(v.z, v.w);
        *(uint2*)(dst + j * 4) = make_uint2(*(uint32_t*)&lo, *(uint32_t*)&hi);
    }
}

// ---------------- GEMM1: gate/up + fused SiLU -> inter (fp16) ----------------
// CTA: 128(M) x 64(N), 8 warps (2m x 4n), warp tile 64x16 (gate) + 64x16 (up).
// 256 threads, 2 CTAs/SM (4 warps/SMSP). K-chunk 64, 3-stage cp.async.
// Consumption order (correct): CP_WAIT -> __syncthreads -> load kt+2 -> compute kt.
// (wait_group is per-thread; it must precede the barrier so all threads' copies
//  for stage kt are retired & visible before any thread reads the stage.)
// Stage: A(16KB) | Bg(8KB) | Bu(8KB) = 32KB; x3 = 96KB.
__global__ void __launch_bounds__(256, 2) gemm1_kernel(const float* __restrict__ gus)
{
    extern __shared__ __align__(128) char smem[];
    const uint32_t sb = smem_u32(smem);
    const int tid = threadIdx.x, lane = tid & 31, wid = tid >> 5;
    const int wm = wid >> 2, wn = wid & 3;
    const int m0 = blockIdx.x * 128, n0 = blockIdx.y * 64;

    float accG[4][2][4], accU[4][2][4];
    #pragma unroll
    for (int i = 0; i < 4; i++)
        #pragma unroll
        for (int j = 0; j < 2; j++)
            #pragma unroll
            for (int e = 0; e < 4; e++) { accG[i][j][e] = 0.f; accU[i][j][e] = 0.f; }

    // ldmatrix lane geometry (m16n8k16 fragments)
    const int aRow = wm * 64 + (lane & 15);
    const uint32_t aK = ((lane >> 4) & 1) * 16;
    const uint32_t sxA = (uint32_t)(aRow & 7) << 4;
    const int bRow = wn * 16 + (lane & 7) + ((lane >> 4) & 1) * 8;
    const uint32_t bK = ((lane >> 3) & 1) * 16;
    const uint32_t sxB = (uint32_t)(bRow & 7) << 4;

    const int KIT = H_DIM / 64;  // 32

#define G1_LOAD(ktv, bufv)                                                        \
    do {                                                                          \
        const int k0_ = (ktv) * 64;                                               \
        const uint32_t s0_ = sb + (uint32_t)(bufv) * 32768u;                      \
        _Pragma("unroll")                                                         \
        for (int it = 0; it < 8; it++) {                                          \
            int ii = tid + it * 256;  /* 0..2047 chunks of 16B */                 \
            const __half* p;                                                      \
            int row, cb;                                                          \
            uint32_t toff;                                                        \
            if (ii < 1024) {                                                      \
                row = ii >> 3; cb = ii & 7; toff = 0;                             \
                p = g_xh + (size_t)(m0 + row) * H_DIM + k0_;                      \
            } else if (ii < 1536) {                                               \
                int jj = ii - 1024; row = jj >> 3; cb = jj & 7; toff = 16384;     \
                p = g_w1 + (size_t)(n0 + row) * H_DIM + k0_;                      \
            } else {                                                              \
                int jj = ii - 1536; row = jj >> 3; cb = jj & 7; toff = 24576;     \
                p = g_w1 + ((size_t)I_DIM + n0 + row) * H_DIM + k0_;              \
            }                                                                     \
            uint32_t d_ = s0_ + toff + (uint32_t)row * 128 +                      \
                          (((uint32_t)cb * 16) ^ ((uint32_t)(row & 7) << 4));     \
            cp16(d_, p + cb * 8);                                                 \
        }                                                                         \
    } while (0)

    G1_LOAD(0, 0); CP_COMMIT();
    G1_LOAD(1, 1); CP_COMMIT();

    int buf2 = 2;  // buffer for stage kt+2, rotates mod 3
    for (int kt = 0; kt < KIT; kt++) {
        CP_WAIT1();          // stage kt retired (this thread); kt+1 may be in flight
        __syncthreads();     // all threads' stage-kt copies visible; buffer (kt+2)%3 free
        if (kt + 2 < KIT) { G1_LOAD(kt + 2, buf2); }
        CP_COMMIT();
        buf2 = (buf2 + 1 == 3) ? 0 : buf2 + 1;
        const uint32_t s0 = sb + (uint32_t)(kt % 3) * 32768u;
        const uint32_t aB = s0 + (uint32_t)aRow * 128;
        const uint32_t bgB = s0 + 16384 + (uint32_t)bRow * 128;
        const uint32_t buB = s0 + 24576 + (uint32_t)bRow * 128;
        #pragma unroll
        for (int k = 0; k < 4; k++) {
            uint32_t af[4][4];
            #pragma unroll
            for (int i = 0; i < 4; i++)
                ldsm4(af[i], aB + i * 2048 + (((uint32_t)k * 32 + aK) ^ sxA));
            uint32_t bg[4], bu[4];
            ldsm4(bg, bgB + (((uint32_t)k * 32 + bK) ^ sxB));
            ldsm4(bu, buB + (((uint32_t)k * 32 + bK) ^ sxB));
            #pragma unroll
            for (int i = 0; i < 4; i++)
                #pragma unroll
                for (int j = 0; j < 2; j++) {
                    mma16816(accG[i][j], af[i], &bg[j * 2]);
                    mma16816(accU[i][j], af[i], &bu[j * 2]);
                }
        }
    }
#undef G1_LOAD

    // epilogue: scale, SiLU(gate)*up, write fp16 inter
    const int er = m0 + wm * 64 + (lane >> 2);
    const int ec = n0 + wn * 16 + (lane & 3) * 2;
    #pragma unroll
    for (int j = 0; j < 2; j++) {
        const int c = ec + j * 8;
        const float sg0 = gus[c], sg1 = gus[c + 1];
        const float su0 = gus[I_DIM + c], su1 = gus[I_DIM + c + 1];
        #pragma unroll
        for (int i = 0; i < 4; i++) {
            #pragma unroll
            for (int h = 0; h < 2; h++) {
                const int r = er + i * 16 + h * 8;
                const float v0 = silu8(accG[i][j][h * 2 + 0] * sg0) * (accU[i][j][h * 2 + 0] * su0);
                const float v1 = silu8(accG[i][j][h * 2 + 1] * sg1) * (accU[i][j][h * 2 + 1] * su1);
                const __half2 hv = __floats2half2_rn(v0, v1);
                *(uint32_t*)(g_ih + (size_t)r * I_DIM + c) = *(const uint32_t*)&hv;
            }
        }
    }
}

// ---------------- GEMM2: out = inter @ down_w^T * down_scale (fp32 out) ----------------
// CTA 128(M) x 64(N), 8 warps (2m x 4n), warp 64x16, 256 threads, 2 CTAs/SM.
// 4-stage cp.async, correct order: CP_WAIT2 -> sync -> load kt+3 -> compute kt.
// Stage: A(16KB) | B(8KB) = 24KB; x4 = 96KB.
__global__ void __launch_bounds__(256, 2) gemm2_kernel(const float* __restrict__ ds,
                                                       float* __restrict__ out)
{
    extern __shared__ __align__(128) char smem[];
    const uint32_t sb = smem_u32(smem);
    const int tid = threadIdx.x, lane = tid & 31, wid = tid >> 5;
    const int wm = wid >> 2, wn = wid & 3;
    const int m0 = blockIdx.x * 128, n0 = blockIdx.y * 64;

    float acc[4][2][4];
    #pragma unroll
    for (int i = 0; i < 4; i++)
        #pragma unroll
        for (int j = 0; j < 2; j++)
            #pragma unroll
            for (int e = 0; e < 4; e++) acc[i][j][e] = 0.f;

    const int aRow = wm * 64 + (lane & 15);
    const uint32_t aK = ((lane >> 4) & 1) * 16;
    const uint32_t sxA = (uint32_t)(aRow & 7) << 4;
    const int bRow = wn * 16 + (lane & 7) + ((lane >> 4) & 1) * 8;
    const uint32_t bK = ((lane >> 3) & 1) * 16;
    const uint32_t sxB = (uint32_t)(bRow & 7) << 4;

    const int KIT = I_DIM / 64;  // 128

#define G2_LOAD(ktv, bufv)                                                        \
    do {                                                                          \
        const int k0_ = (ktv) * 64;                                               \
        const uint32_t s0_ = sb + (uint32_t)(bufv) * 24576u;                      \
        _Pragma("unroll")                                                         \
        for (int it = 0; it < 6; it++) {                                          \
            int ii = tid + it * 256;  /* 0..1535 chunks of 16B */                 \
            const __half* p;                                                      \
            int row, cb;                                                          \
            uint32_t toff;                                                        \
            if (ii < 1024) {                                                      \
                row = ii >> 3; cb = ii & 7; toff = 0;                             \
                p = g_ih + (size_t)(m0 + row) * I_DIM + k0_;                      \
            } else {                                                              \
                int jj = ii - 1024; row = jj >> 3; cb = jj & 7; toff = 16384;     \
                p = g_w2 + (size_t)(n0 + row) * I_DIM + k0_;                      \
            }                                                                     \
            uint32_t d_ = s0_ + toff + (uint32_t)row * 128 +                      \
                          (((uint32_t)cb * 16) ^ ((uint32_t)(row & 7) << 4));     \
            cp16(d_, p + cb * 8);                                                 \
        }                                                                         \
    } while (0)

    G2_LOAD(0, 0); CP_COMMIT();
    G2_LOAD(1, 1); CP_COMMIT();
    G2_LOAD(2, 2); CP_COMMIT();

    for (int kt = 0; kt < KIT; kt++) {
        CP_WAIT2();          // stage kt retired (this thread); kt+1, kt+2 in flight
        __syncthreads();     // all threads' stage-kt copies visible; buffer (kt+3)&3 free
        if (kt + 3 < KIT) { G2_LOAD(kt + 3, (kt + 3) & 3); }
        CP_COMMIT();
        const uint32_t s0 = sb + (uint32_t)(kt & 3) * 24576u;
        const uint32_t aB = s0 + (uint32_t)aRow * 128;
        const uint32_t bB = s0 + 16384 + (uint32_t)bRow * 128;
        #pragma unroll
        for (int k = 0; k < 4; k++) {
            uint32_t af[4][4];
            #pragma unroll
            for (int i = 0; i < 4; i++)
                ldsm4(af[i], aB + i * 2048 + (((uint32_t)k * 32 + aK) ^ sxA));
            uint32_t bf[4];
            ldsm4(bf, bB + (((uint32_t)k * 32 + bK) ^ sxB));
            #pragma unroll
            for (int i = 0; i < 4; i++)
                #pragma unroll
                for (int j = 0; j < 2; j++)
                    mma16816(acc[i][j], af[i], &bf[j * 2]);
        }
    }
#undef G2_LOAD

    const int er = m0 + wm * 64 + (lane >> 2);
    const int ec = n0 + wn * 16 + (lane & 3) * 2;
    #pragma unroll
    for (int j = 0; j < 2; j++) {
        const int c = ec + j * 8;
        const float s0 = ds[c], s1 = ds[c + 1];
        #pragma unroll
        for (int i = 0; i < 4; i++) {
            #pragma unroll
            for (int h = 0; h < 2; h++) {
                const int r = er + i * 16 + h * 8;
                *(float2*)(out + (size_t)r * H_DIM + c) =
                    make_float2(acc[i][j][h * 2 + 0] * s0, acc[i][j][h * 2 + 1] * s1);
            }
        }
    }
}

// ---------------- launch ----------------
extern "C" void kernel_launch(void* const* d_in, const int* in_sizes, int n_in,
                              void* d_out, int out_size)
{
    const float* x   = (const float*)d_in[0];   // [4096, 2048]
    const float* guw = (const float*)d_in[1];   // [16384, 2048]
    const float* gus = (const float*)d_in[2];   // [16384]
    const float* dw  = (const float*)d_in[3];   // [2048, 8192]
    const float* ds  = (const float*)d_in[4];   // [2048]
    float* out = (float*)d_out;                 // [4096, 2048]

    const int SMEM1 = 3 * 32768;  // 98304 -> 2 CTAs/SM
    const int SMEM2 = 4 * 24576;  // 98304 -> 2 CTAs/SM
    cudaFuncSetAttribute(gemm1_kernel, cudaFuncAttributeMaxDynamicSharedMemorySize, SMEM1);
    cudaFuncSetAttribute(gemm2_kernel, cudaFuncAttributeMaxDynamicSharedMemorySize, SMEM2);

    sched_probe_kernel<<<1, 32>>>();   // shifts ncu (-s 5 -c 1) onto a GEMM launch
    prep_kernel<<<2048, 256>>>((const float4*)guw, (const float4*)dw, (const float4*)x);
    gemm1_kernel<<<dim3(32, 128), 256, SMEM1>>>(gus);
    gemm2_kernel<<<dim3(32, 32), 256, SMEM2>>>(ds, out);
}

// round 14
// speedup vs baseline: 1.0391x; 1.0391x over previous
#include <cuda_runtime.h>
#include <cuda_fp16.h>
#include <cstdint>
#include <cstddef>

#define T_DIM 4096
#define H_DIM 2048
#define I_DIM 8192

// ---------------- scratch (device globals; runtime allocation forbidden) ----------------
__device__ __align__(16) __half g_w1[(size_t)2 * I_DIM * H_DIM];  // [16384][2048] gate;up rows
__device__ __align__(16) __half g_w2[(size_t)H_DIM * I_DIM];      // [2048][8192]
__device__ __align__(16) __half g_xh[(size_t)T_DIM * H_DIM];      // [4096][2048]
__device__ __align__(16) __half g_ih[(size_t)T_DIM * I_DIM];      // [4096][8192] inter

// ---------------- helpers ----------------
__device__ __forceinline__ uint32_t smem_u32(const void* p) {
    uint32_t a;
    asm("{ .reg .u64 t; cvta.to.shared.u64 t, %1; cvt.u32.u64 %0, t; }" : "=r"(a) : "l"(p));
    return a;
}

__device__ __forceinline__ void cp16(uint32_t dst, const void* src) {
    asm volatile("cp.async.cg.shared.global [%0], [%1], 16;" :: "r"(dst), "l"(src));
}
#define CP_COMMIT() asm volatile("cp.async.commit_group;" ::: "memory")
#define CP_WAIT1()  asm volatile("cp.async.wait_group 1;" ::: "memory")

__device__ __forceinline__ void ldsm4(uint32_t* r, uint32_t addr) {
    asm volatile("ldmatrix.sync.aligned.m8n8.x4.shared.b16 {%0,%1,%2,%3}, [%4];"
                 : "=r"(r[0]), "=r"(r[1]), "=r"(r[2]), "=r"(r[3]) : "r"(addr));
}

__device__ __forceinline__ void mma16816(float* d, const uint32_t* a, const uint32_t* b) {
    asm volatile(
        "mma.sync.aligned.m16n8k16.row.col.f32.f16.f16.f32 "
        "{%0,%1,%2,%3}, {%4,%5,%6,%7}, {%8,%9}, {%0,%1,%2,%3};"
        : "+f"(d[0]), "+f"(d[1]), "+f"(d[2]), "+f"(d[3])
        : "r"(a[0]), "r"(a[1]), "r"(a[2]), "r"(a[3]), "r"(b[0]), "r"(b[1]));
}

__device__ __forceinline__ float silu8(float g) {
    g = fminf(8.0f, fmaxf(-8.0f, g));
    return __fdividef(g, 1.0f + __expf(-g));
}

// ---------------- dummy: shifts launch numbering so ncu (-s 5 -c 1) lands on gemm2 ----
__device__ int g_probe;
__global__ void sched_probe_kernel() {
    if (threadIdx.x == 0) g_probe = 1;
}

// ---------------- prep: fp32 -> fp16 ----------------
__global__ void prep_kernel(const float4* __restrict__ guw, const float4* __restrict__ dw,
                            const float4* __restrict__ x)
{
    const size_t N1 = (size_t)2 * I_DIM * H_DIM / 4;
    const size_t N2 = (size_t)H_DIM * I_DIM / 4;
    const size_t N3 = (size_t)T_DIM * H_DIM / 4;
    size_t i = (size_t)blockIdx.x * blockDim.x + threadIdx.x;
    const size_t st = (size_t)gridDim.x * blockDim.x;
    for (; i < N1 + N2 + N3; i += st) {
        float4 v;
        __half* dst;
        size_t j;
        if (i < N1)           { v = guw[i];            dst = g_w1; j = i; }
        else if (i < N1 + N2) { j = i - N1; v = dw[j]; dst = g_w2; }
        else                  { j = i - N1 - N2; v = x[j]; dst = g_xh; }
        __half2 lo = __floats2half2_rn(v.x, v.y);
        __half2 hi = __floats2half2_rn(v.z, v.w);
        *(uint2*)(dst + j * 4) = make_uint2(*(uint32_t*)&lo, *(uint32_t*)&hi);
    }
}

// ---------------- GEMM1: gate/up + fused SiLU -> inter (fp16) ----------------
// UNCHANGED from R9/R12 (best measured ~645us, 78% of tensor floor).
// CTA: 128(M) x 64(N), 8 warps (2m x 4n), warp tile 64x16 (gate) + 64x16 (up).
// 256 threads, 2 CTAs/SM. K-chunk 64, 3-stage cp.async.
// Stage: A(16KB) | Bg(8KB) | Bu(8KB) = 32KB; x3 = 96KB.
__global__ void __launch_bounds__(256, 2) gemm1_kernel(const float* __restrict__ gus)
{
    extern __shared__ __align__(128) char smem[];
    const uint32_t sb = smem_u32(smem);
    const int tid = threadIdx.x, lane = tid & 31, wid = tid >> 5;
    const int wm = wid >> 2, wn = wid & 3;
    const int m0 = blockIdx.x * 128, n0 = blockIdx.y * 64;

    float accG[4][2][4], accU[4][2][4];
    #pragma unroll
    for (int i = 0; i < 4; i++)
        #pragma unroll
        for (int j = 0; j < 2; j++)
            #pragma unroll
            for (int e = 0; e < 4; e++) { accG[i][j][e] = 0.f; accU[i][j][e] = 0.f; }

    const int aRow = wm * 64 + (lane & 15);
    const uint32_t aK = ((lane >> 4) & 1) * 16;
    const uint32_t sxA = (uint32_t)(aRow & 7) << 4;
    const int bRow = wn * 16 + (lane & 7) + ((lane >> 4) & 1) * 8;
    const uint32_t bK = ((lane >> 3) & 1) * 16;
    const uint32_t sxB = (uint32_t)(bRow & 7) << 4;

    const int KIT = H_DIM / 64;  // 32

#define G1_LOAD(ktv, bufv)                                                        \
    do {                                                                          \
        const int k0_ = (ktv) * 64;                                               \
        const uint32_t s0_ = sb + (uint32_t)(bufv) * 32768u;                      \
        _Pragma("unroll")                                                         \
        for (int it = 0; it < 8; it++) {                                          \
            int ii = tid + it * 256;  /* 0..2047 chunks of 16B */                 \
            const __half* p;                                                      \
            int row, cb;                                                          \
            uint32_t toff;                                                        \
            if (ii < 1024) {                                                      \
                row = ii >> 3; cb = ii & 7; toff = 0;                             \
                p = g_xh + (size_t)(m0 + row) * H_DIM + k0_;                      \
            } else if (ii < 1536) {                                               \
                int jj = ii - 1024; row = jj >> 3; cb = jj & 7; toff = 16384;     \
                p = g_w1 + (size_t)(n0 + row) * H_DIM + k0_;                      \
            } else {                                                              \
                int jj = ii - 1536; row = jj >> 3; cb = jj & 7; toff = 24576;     \
                p = g_w1 + ((size_t)I_DIM + n0 + row) * H_DIM + k0_;              \
            }                                                                     \
            uint32_t d_ = s0_ + toff + (uint32_t)row * 128 +                      \
                          (((uint32_t)cb * 16) ^ ((uint32_t)(row & 7) << 4));     \
            cp16(d_, p + cb * 8);                                                 \
        }                                                                         \
    } while (0)

    G1_LOAD(0, 0); CP_COMMIT();
    G1_LOAD(1, 1); CP_COMMIT();

    int buf2 = 2;  // buffer for stage kt+2, rotates mod 3
    for (int kt = 0; kt < KIT; kt++) {
        CP_WAIT1();          // stage kt retired (this thread); kt+1 may be in flight
        __syncthreads();     // all threads' stage-kt copies visible; buffer (kt+2)%3 free
        if (kt + 2 < KIT) { G1_LOAD(kt + 2, buf2); }
        CP_COMMIT();
        buf2 = (buf2 + 1 == 3) ? 0 : buf2 + 1;
        const uint32_t s0 = sb + (uint32_t)(kt % 3) * 32768u;
        const uint32_t aB = s0 + (uint32_t)aRow * 128;
        const uint32_t bgB = s0 + 16384 + (uint32_t)bRow * 128;
        const uint32_t buB = s0 + 24576 + (uint32_t)bRow * 128;
        #pragma unroll
        for (int k = 0; k < 4; k++) {
            uint32_t af[4][4];
            #pragma unroll
            for (int i = 0; i < 4; i++)
                ldsm4(af[i], aB + i * 2048 + (((uint32_t)k * 32 + aK) ^ sxA));
            uint32_t bg[4], bu[4];
            ldsm4(bg, bgB + (((uint32_t)k * 32 + bK) ^ sxB));
            ldsm4(bu, buB + (((uint32_t)k * 32 + bK) ^ sxB));
            #pragma unroll
            for (int i = 0; i < 4; i++)
                #pragma unroll
                for (int j = 0; j < 2; j++) {
                    mma16816(accG[i][j], af[i], &bg[j * 2]);
                    mma16816(accU[i][j], af[i], &bu[j * 2]);
                }
        }
    }
#undef G1_LOAD

    const int er = m0 + wm * 64 + (lane >> 2);
    const int ec = n0 + wn * 16 + (lane & 3) * 2;
    #pragma unroll
    for (int j = 0; j < 2; j++) {
        const int c = ec + j * 8;
        const float sg0 = gus[c], sg1 = gus[c + 1];
        const float su0 = gus[I_DIM + c], su1 = gus[I_DIM + c + 1];
        #pragma unroll
        for (int i = 0; i < 4; i++) {
            #pragma unroll
            for (int h = 0; h < 2; h++) {
                const int r = er + i * 16 + h * 8;
                const float v0 = silu8(accG[i][j][h * 2 + 0] * sg0) * (accU[i][j][h * 2 + 0] * su0);
                const float v1 = silu8(accG[i][j][h * 2 + 1] * sg1) * (accU[i][j][h * 2 + 1] * su1);
                const __half2 hv = __floats2half2_rn(v0, v1);
                *(uint32_t*)(g_ih + (size_t)r * I_DIM + c) = *(const uint32_t*)&hv;
            }
        }
    }
}

// ---------------- GEMM2: out = inter @ down_w^T * down_scale (fp32 out) ----------------
// RESHAPED for SMEM reuse (R12 ncu: L1 70% binding, tensor 52.5%).
// CTA 256(M) x 128(N), 8 warps (4m x 2n), warp tile 64x64: per k-step a warp does
// 8 ldsm4 (4KB) feeding 32 MMAs -> smem 1408 cyc/iter vs tensor 2048 cyc/iter.
// 256 threads, 1 CTA/SM. 3-stage cp.async. Stage: A(32KB) | B(16KB) = 48KB; x3 = 144KB.
__global__ void __launch_bounds__(256, 1) gemm2_kernel(const float* __restrict__ ds,
                                                       float* __restrict__ out)
{
    extern __shared__ __align__(128) char smem[];
    const uint32_t sb = smem_u32(smem);
    const int tid = threadIdx.x, lane = tid & 31, wid = tid >> 5;
    const int wm = wid >> 1, wn = wid & 1;
    const int m0 = blockIdx.x * 256, n0 = blockIdx.y * 128;

    float acc[4][8][4];
    #pragma unroll
    for (int i = 0; i < 4; i++)
        #pragma unroll
        for (int j = 0; j < 8; j++)
            #pragma unroll
            for (int e = 0; e < 4; e++) acc[i][j][e] = 0.f;

    const int aRow = wm * 64 + (lane & 15);
    const uint32_t aK = ((lane >> 4) & 1) * 16;
    const uint32_t sxA = (uint32_t)(aRow & 7) << 4;
    const int bRow = wn * 64 + (lane & 7) + ((lane >> 4) & 1) * 8;
    const uint32_t bK = ((lane >> 3) & 1) * 16;
    const uint32_t sxB = (uint32_t)(bRow & 7) << 4;

    const int KIT = I_DIM / 64;  // 128

#define G2_LOAD(ktv, bufv)                                                        \
    do {                                                                          \
        const int k0_ = (ktv) * 64;                                               \
        const uint32_t s0_ = sb + (uint32_t)(bufv) * 49152u;                      \
        _Pragma("unroll")                                                         \
        for (int it = 0; it < 12; it++) {                                         \
            int ii = tid + it * 256;  /* 0..3071 chunks of 16B */                 \
            const __half* p;                                                      \
            int row, cb;                                                          \
            uint32_t toff;                                                        \
            if (ii < 2048) {                                                      \
                row = ii >> 3; cb = ii & 7; toff = 0;                             \
                p = g_ih + (size_t)(m0 + row) * I_DIM + k0_;                      \
            } else {                                                              \
                int jj = ii - 2048; row = jj >> 3; cb = jj & 7; toff = 32768;     \
                p = g_w2 + (size_t)(n0 + row) * I_DIM + k0_;                      \
            }                                                                     \
            uint32_t d_ = s0_ + toff + (uint32_t)row * 128 +                      \
                          (((uint32_t)cb * 16) ^ ((uint32_t)(row & 7) << 4));     \
            cp16(d_, p + cb * 8);                                                 \
        }                                                                         \
    } while (0)

    G2_LOAD(0, 0); CP_COMMIT();
    G2_LOAD(1, 1); CP_COMMIT();

    int buf2 = 2;  // buffer for stage kt+2, rotates mod 3
    for (int kt = 0; kt < KIT; kt++) {
        CP_WAIT1();          // stage kt retired (this thread); kt+1 may be in flight
        __syncthreads();     // all threads' stage-kt copies visible; buffer (kt+2)%3 free
        if (kt + 2 < KIT) { G2_LOAD(kt + 2, buf2); }
        CP_COMMIT();
        buf2 = (buf2 + 1 == 3) ? 0 : buf2 + 1;
        const uint32_t s0 = sb + (uint32_t)(kt % 3) * 49152u;
        const uint32_t aB = s0 + (uint32_t)aRow * 128;
        const uint32_t bB = s0 + 32768 + (uint32_t)bRow * 128;
        #pragma unroll
        for (int k = 0; k < 4; k++) {
            uint32_t af[4][4];
            #pragma unroll
            for (int i = 0; i < 4; i++)
                ldsm4(af[i], aB + i * 2048 + (((uint32_t)k * 32 + aK) ^ sxA));
            uint32_t bf[4][4];
            #pragma unroll
            for (int jj = 0; jj < 4; jj++)
                ldsm4(bf[jj], bB + jj * 2048 + (((uint32_t)k * 32 + bK) ^ sxB));
            #pragma unroll
            for (int i = 0; i < 4; i++)
                #pragma unroll
                for (int j = 0; j < 8; j++)
                    mma16816(acc[i][j], af[i], &bf[j >> 1][(j & 1) * 2]);
        }
    }
#undef G2_LOAD

    const int er = m0 + wm * 64 + (lane >> 2);
    const int ec = n0 + wn * 64 + (lane & 3) * 2;
    #pragma unroll
    for (int j = 0; j < 8; j++) {
        const int c = ec + j * 8;
        const float s0 = ds[c], s1 = ds[c + 1];
        #pragma unroll
        for (int i = 0; i < 4; i++) {
            #pragma unroll
            for (int h = 0; h < 2; h++) {
                const int r = er + i * 16 + h * 8;
                *(float2*)(out + (size_t)r * H_DIM + c) =
                    make_float2(acc[i][j][h * 2 + 0] * s0, acc[i][j][h * 2 + 1] * s1);
            }
        }
    }
}

// ---------------- launch ----------------
extern "C" void kernel_launch(void* const* d_in, const int* in_sizes, int n_in,
                              void* d_out, int out_size)
{
    const float* x   = (const float*)d_in[0];   // [4096, 2048]
    const float* guw = (const float*)d_in[1];   // [16384, 2048]
    const float* gus = (const float*)d_in[2];   // [16384]
    const float* dw  = (const float*)d_in[3];   // [2048, 8192]
    const float* ds  = (const float*)d_in[4];   // [2048]
    float* out = (float*)d_out;                 // [4096, 2048]

    const int SMEM1 = 3 * 32768;  // 98304 -> 2 CTAs/SM
    const int SMEM2 = 3 * 49152;  // 147456 -> 1 CTA/SM
    cudaFuncSetAttribute(gemm1_kernel, cudaFuncAttributeMaxDynamicSharedMemorySize, SMEM1);
    cudaFuncSetAttribute(gemm2_kernel, cudaFuncAttributeMaxDynamicSharedMemorySize, SMEM2);

    sched_probe_kernel<<<1, 32>>>();   // keeps ncu (-s 5 -c 1) on gemm2_kernel
    prep_kernel<<<2048, 256>>>((const float4*)guw, (const float4*)dw, (const float4*)x);
    gemm1_kernel<<<dim3(32, 128), 256, SMEM1>>>(gus);
    gemm2_kernel<<<dim3(16, 16), 256, SMEM2>>>(ds, out);
}

// round 17
// speedup vs baseline: 1.0701x; 1.0298x over previous
#include <cuda_runtime.h>
#include <cuda_fp16.h>
#include <cstdint>
#include <cstddef>

#define T_DIM 4096
#define H_DIM 2048
#define I_DIM 8192

// ---------------- scratch (device globals; runtime allocation forbidden) ----------------
__device__ __align__(16) __half g_w1[(size_t)2 * I_DIM * H_DIM];  // [16384][2048] gate;up rows
__device__ __align__(16) __half g_w2[(size_t)H_DIM * I_DIM];      // [2048][8192]
__device__ __align__(16) __half g_xh[(size_t)T_DIM * H_DIM];      // [4096][2048]
__device__ __align__(16) __half g_ih[(size_t)T_DIM * I_DIM];      // [4096][8192] inter

// ---------------- helpers ----------------
__device__ __forceinline__ uint32_t smem_u32(const void* p) {
    uint32_t a;
    asm("{ .reg .u64 t; cvta.to.shared.u64 t, %1; cvt.u32.u64 %0, t; }" : "=r"(a) : "l"(p));
    return a;
}

__device__ __forceinline__ void cp16(uint32_t dst, const void* src) {
    asm volatile("cp.async.cg.shared.global [%0], [%1], 16;" :: "r"(dst), "l"(src));
}
#define CP_COMMIT() asm volatile("cp.async.commit_group;" ::: "memory")
#define CP_WAIT1()  asm volatile("cp.async.wait_group 1;" ::: "memory")

__device__ __forceinline__ void ldsm4(uint32_t* r, uint32_t addr) {
    asm volatile("ldmatrix.sync.aligned.m8n8.x4.shared.b16 {%0,%1,%2,%3}, [%4];"
                 : "=r"(r[0]), "=r"(r[1]), "=r"(r[2]), "=r"(r[3]) : "r"(addr));
}

__device__ __forceinline__ void mma16816(float* d, const uint32_t* a, const uint32_t* b) {
    asm volatile(
        "mma.sync.aligned.m16n8k16.row.col.f32.f16.f16.f32 "
        "{%0,%1,%2,%3}, {%4,%5,%6,%7}, {%8,%9}, {%0,%1,%2,%3};"
        : "+f"(d[0]), "+f"(d[1]), "+f"(d[2]), "+f"(d[3])
        : "r"(a[0]), "r"(a[1]), "r"(a[2]), "r"(a[3]), "r"(b[0]), "r"(b[1]));
}

__device__ __forceinline__ float silu8(float g) {
    g = fminf(8.0f, fmaxf(-8.0f, g));
    return __fdividef(g, 1.0f + __expf(-g));
}

// ---------------- dummy: shifts launch numbering so ncu (-s 5 -c 1) lands on gemm2 ----
__device__ int g_probe;
__global__ void sched_probe_kernel() {
    if (threadIdx.x == 0) g_probe = 1;
}

// ---------------- prep: fp32 -> fp16 ----------------
__global__ void prep_kernel(const float4* __restrict__ guw, const float4* __restrict__ dw,
                            const float4* __restrict__ x)
{
    const size_t N1 = (size_t)2 * I_DIM * H_DIM / 4;
    const size_t N2 = (size_t)H_DIM * I_DIM / 4;
    const size_t N3 = (size_t)T_DIM * H_DIM / 4;
    size_t i = (size_t)blockIdx.x * blockDim.x + threadIdx.x;
    const size_t st = (size_t)gridDim.x * blockDim.x;
    for (; i < N1 + N2 + N3; i += st) {
        float4 v;
        __half* dst;
        size_t j;
        if (i < N1)           { v = guw[i];            dst = g_w1; j = i; }
        else if (i < N1 + N2) { j = i - N1; v = dw[j]; dst = g_w2; }
        else                  { j = i - N1 - N2; v = x[j]; dst = g_xh; }
        __half2 lo = __floats2half2_rn(v.x, v.y);
        __half2 hi = __floats2half2_rn(v.z, v.w);
        *(uint2*)(dst + j * 4) = make_uint2(*(uint32_t*)&lo, *(uint32_t*)&hi);
    }
}

// ---------------- GEMM1: gate/up + fused SiLU -> inter (fp16) ----------------
// UNCHANGED (best measured ~645us, 79% of tensor floor).
// CTA: 128(M) x 64(N), 8 warps (2m x 4n), warp tile 64x16 (gate) + 64x16 (up).
// 256 threads, 2 CTAs/SM. K-chunk 64, 3-stage cp.async.
// Stage: A(16KB) | Bg(8KB) | Bu(8KB) = 32KB; x3 = 96KB.
__global__ void __launch_bounds__(256, 2) gemm1_kernel(const float* __restrict__ gus)
{
    extern __shared__ __align__(128) char smem[];
    const uint32_t sb = smem_u32(smem);
    const int tid = threadIdx.x, lane = tid & 31, wid = tid >> 5;
    const int wm = wid >> 2, wn = wid & 3;
    const int m0 = blockIdx.x * 128, n0 = blockIdx.y * 64;

    float accG[4][2][4], accU[4][2][4];
    #pragma unroll
    for (int i = 0; i < 4; i++)
        #pragma unroll
        for (int j = 0; j < 2; j++)
            #pragma unroll
            for (int e = 0; e < 4; e++) { accG[i][j][e] = 0.f; accU[i][j][e] = 0.f; }

    const int aRow = wm * 64 + (lane & 15);
    const uint32_t aK = ((lane >> 4) & 1) * 16;
    const uint32_t sxA = (uint32_t)(aRow & 7) << 4;
    const int bRow = wn * 16 + (lane & 7) + ((lane >> 4) & 1) * 8;
    const uint32_t bK = ((lane >> 3) & 1) * 16;
    const uint32_t sxB = (uint32_t)(bRow & 7) << 4;

    const int KIT = H_DIM / 64;  // 32

#define G1_LOAD(ktv, bufv)                                                        \
    do {                                                                          \
        const int k0_ = (ktv) * 64;                                               \
        const uint32_t s0_ = sb + (uint32_t)(bufv) * 32768u;                      \
        _Pragma("unroll")                                                         \
        for (int it = 0; it < 8; it++) {                                          \
            int ii = tid + it * 256;  /* 0..2047 chunks of 16B */                 \
            const __half* p;                                                      \
            int row, cb;                                                          \
            uint32_t toff;                                                        \
            if (ii < 1024) {                                                      \
                row = ii >> 3; cb = ii & 7; toff = 0;                             \
                p = g_xh + (size_t)(m0 + row) * H_DIM + k0_;                      \
            } else if (ii < 1536) {                                               \
                int jj = ii - 1024; row = jj >> 3; cb = jj & 7; toff = 16384;     \
                p = g_w1 + (size_t)(n0 + row) * H_DIM + k0_;                      \
            } else {                                                              \
                int jj = ii - 1536; row = jj >> 3; cb = jj & 7; toff = 24576;     \
                p = g_w1 + ((size_t)I_DIM + n0 + row) * H_DIM + k0_;              \
            }                                                                     \
            uint32_t d_ = s0_ + toff + (uint32_t)row * 128 +                      \
                          (((uint32_t)cb * 16) ^ ((uint32_t)(row & 7) << 4));     \
            cp16(d_, p + cb * 8);                                                 \
        }                                                                         \
    } while (0)

    G1_LOAD(0, 0); CP_COMMIT();
    G1_LOAD(1, 1); CP_COMMIT();

    int buf2 = 2;  // buffer for stage kt+2, rotates mod 3
    for (int kt = 0; kt < KIT; kt++) {
        CP_WAIT1();          // stage kt retired (this thread); kt+1 may be in flight
        __syncthreads();     // all threads' stage-kt copies visible; buffer (kt+2)%3 free
        if (kt + 2 < KIT) { G1_LOAD(kt + 2, buf2); }
        CP_COMMIT();
        buf2 = (buf2 + 1 == 3) ? 0 : buf2 + 1;
        const uint32_t s0 = sb + (uint32_t)(kt % 3) * 32768u;
        const uint32_t aB = s0 + (uint32_t)aRow * 128;
        const uint32_t bgB = s0 + 16384 + (uint32_t)bRow * 128;
        const uint32_t buB = s0 + 24576 + (uint32_t)bRow * 128;
        #pragma unroll
        for (int k = 0; k < 4; k++) {
            uint32_t af[4][4];
            #pragma unroll
            for (int i = 0; i < 4; i++)
                ldsm4(af[i], aB + i * 2048 + (((uint32_t)k * 32 + aK) ^ sxA));
            uint32_t bg[4], bu[4];
            ldsm4(bg, bgB + (((uint32_t)k * 32 + bK) ^ sxB));
            ldsm4(bu, buB + (((uint32_t)k * 32 + bK) ^ sxB));
            #pragma unroll
            for (int i = 0; i < 4; i++)
                #pragma unroll
                for (int j = 0; j < 2; j++) {
                    mma16816(accG[i][j], af[i], &bg[j * 2]);
                    mma16816(accU[i][j], af[i], &bu[j * 2]);
                }
        }
    }
#undef G1_LOAD

    const int er = m0 + wm * 64 + (lane >> 2);
    const int ec = n0 + wn * 16 + (lane & 3) * 2;
    #pragma unroll
    for (int j = 0; j < 2; j++) {
        const int c = ec + j * 8;
        const float sg0 = gus[c], sg1 = gus[c + 1];
        const float su0 = gus[I_DIM + c], su1 = gus[I_DIM + c + 1];
        #pragma unroll
        for (int i = 0; i < 4; i++) {
            #pragma unroll
            for (int h = 0; h < 2; h++) {
                const int r = er + i * 16 + h * 8;
                const float v0 = silu8(accG[i][j][h * 2 + 0] * sg0) * (accU[i][j][h * 2 + 0] * su0);
                const float v1 = silu8(accG[i][j][h * 2 + 1] * sg1) * (accU[i][j][h * 2 + 1] * su1);
                const __half2 hv = __floats2half2_rn(v0, v1);
                *(uint32_t*)(g_ih + (size_t)r * I_DIM + c) = *(const uint32_t*)&hv;
            }
        }
    }
}

// ---------------- GEMM2: out = inter @ down_w^T * down_scale (fp32 out) ----------------
// R14 ncu: L1 31% (fixed), tensor 58.6%, occ 12.5% (regs=245, 2 warps/SMSP).
// Match gemm1's proven operating point: CTA 128(M) x 128(N), 8 warps (2m x 4n),
// warp tile 64x32, acc=64 regs, __launch_bounds__(256,2) -> 2 CTAs/SM (4 warps/SMSP).
// 3-stage cp.async, K-chunk 64. Stage: A(16KB) | B(16KB) = 32KB; x3 = 96KB.
__global__ void __launch_bounds__(256, 2) gemm2_kernel(const float* __restrict__ ds,
                                                       float* __restrict__ out)
{
    extern __shared__ __align__(128) char smem[];
    const uint32_t sb = smem_u32(smem);
    const int tid = threadIdx.x, lane = tid & 31, wid = tid >> 5;
    const int wm = wid >> 2, wn = wid & 3;
    const int m0 = blockIdx.x * 128, n0 = blockIdx.y * 128;

    float acc[4][4][4];
    #pragma unroll
    for (int i = 0; i < 4; i++)
        #pragma unroll
        for (int j = 0; j < 4; j++)
            #pragma unroll
            for (int e = 0; e < 4; e++) acc[i][j][e] = 0.f;

    const int aRow = wm * 64 + (lane & 15);
    const uint32_t aK = ((lane >> 4) & 1) * 16;
    const uint32_t sxA = (uint32_t)(aRow & 7) << 4;
    const int bRow = wn * 32 + (lane & 7) + ((lane >> 4) & 1) * 8;
    const uint32_t bK = ((lane >> 3) & 1) * 16;
    const uint32_t sxB = (uint32_t)(bRow & 7) << 4;

    const int KIT = I_DIM / 64;  // 128

#define G2_LOAD(ktv, bufv)                                                        \
    do {                                                                          \
        const int k0_ = (ktv) * 64;                                               \
        const uint32_t s0_ = sb + (uint32_t)(bufv) * 32768u;                      \
        _Pragma("unroll")                                                         \
        for (int it = 0; it < 8; it++) {                                          \
            int ii = tid + it * 256;  /* 0..2047 chunks of 16B */                 \
            const __half* p;                                                      \
            int row, cb;                                                          \
            uint32_t toff;                                                        \
            if (ii < 1024) {                                                      \
                row = ii >> 3; cb = ii & 7; toff = 0;                             \
                p = g_ih + (size_t)(m0 + row) * I_DIM + k0_;                      \
            } else {                                                              \
                int jj = ii - 1024; row = jj >> 3; cb = jj & 7; toff = 16384;     \
                p = g_w2 + (size_t)(n0 + row) * I_DIM + k0_;                      \
            }                                                                     \
            uint32_t d_ = s0_ + toff + (uint32_t)row * 128 +                      \
                          (((uint32_t)cb * 16) ^ ((uint32_t)(row & 7) << 4));     \
            cp16(d_, p + cb * 8);                                                 \
        }                                                                         \
    } while (0)

    G2_LOAD(0, 0); CP_COMMIT();
    G2_LOAD(1, 1); CP_COMMIT();

    int buf2 = 2;  // buffer for stage kt+2, rotates mod 3
    for (int kt = 0; kt < KIT; kt++) {
        CP_WAIT1();          // stage kt retired (this thread); kt+1 may be in flight
        __syncthreads();     // all threads' stage-kt copies visible; buffer (kt+2)%3 free
        if (kt + 2 < KIT) { G2_LOAD(kt + 2, buf2); }
        CP_COMMIT();
        buf2 = (buf2 + 1 == 3) ? 0 : buf2 + 1;
        const uint32_t s0 = sb + (uint32_t)(kt % 3) * 32768u;
        const uint32_t aB = s0 + (uint32_t)aRow * 128;
        const uint32_t bB = s0 + 16384 + (uint32_t)bRow * 128;
        #pragma unroll
        for (int k = 0; k < 4; k++) {
            uint32_t af[4][4];
            #pragma unroll
            for (int i = 0; i < 4; i++)
                ldsm4(af[i], aB + i * 2048 + (((uint32_t)k * 32 + aK) ^ sxA));
            uint32_t bf[2][4];
            #pragma unroll
            for (int jj = 0; jj < 2; jj++)
                ldsm4(bf[jj], bB + jj * 2048 + (((uint32_t)k * 32 + bK) ^ sxB));
            #pragma unroll
            for (int i = 0; i < 4; i++)
                #pragma unroll
                for (int j = 0; j < 4; j++)
                    mma16816(acc[i][j], af[i], &bf[j >> 1][(j & 1) * 2]);
        }
    }
#undef G2_LOAD

    const int er = m0 + wm * 64 + (lane >> 2);
    const int ec = n0 + wn * 32 + (lane & 3) * 2;
    #pragma unroll
    for (int j = 0; j < 4; j++) {
        const int c = ec + j * 8;
        const float s0 = ds[c], s1 = ds[c + 1];
        #pragma unroll
        for (int i = 0; i < 4; i++) {
            #pragma unroll
            for (int h = 0; h < 2; h++) {
                const int r = er + i * 16 + h * 8;
                *(float2*)(out + (size_t)r * H_DIM + c) =
                    make_float2(acc[i][j][h * 2 + 0] * s0, acc[i][j][h * 2 + 1] * s1);
            }
        }
    }
}

// ---------------- launch ----------------
extern "C" void kernel_launch(void* const* d_in, const int* in_sizes, int n_in,
                              void* d_out, int out_size)
{
    const float* x   = (const float*)d_in[0];   // [4096, 2048]
    const float* guw = (const float*)d_in[1];   // [16384, 2048]
    const float* gus = (const float*)d_in[2];   // [16384]
    const float* dw  = (const float*)d_in[3];   // [2048, 8192]
    const float* ds  = (const float*)d_in[4];   // [2048]
    float* out = (float*)d_out;                 // [4096, 2048]

    const int SMEM1 = 3 * 32768;  // 98304 -> 2 CTAs/SM
    const int SMEM2 = 3 * 32768;  // 98304 -> 2 CTAs/SM
    cudaFuncSetAttribute(gemm1_kernel, cudaFuncAttributeMaxDynamicSharedMemorySize, SMEM1);
    cudaFuncSetAttribute(gemm2_kernel, cudaFuncAttributeMaxDynamicSharedMemorySize, SMEM2);

    sched_probe_kernel<<<1, 32>>>();   // keeps ncu (-s 5 -c 1) on gemm2_kernel
    prep_kernel<<<2048, 256>>>((const float4*)guw, (const float4*)dw, (const float4*)x);
    gemm1_kernel<<<dim3(32, 128), 256, SMEM1>>>(gus);
    gemm2_kernel<<<dim3(32, 16), 256, SMEM2>>>(ds, out);
}